// round 2
// baseline (speedup 1.0000x reference)
#include <cuda_runtime.h>
#include <math.h>

#define Vn 100000
#define Dn 256
#define Bn 512
#define Sn 20
#define Nn (Bn*Sn)      // 10240
#define En (8*Nn)       // 81920

// ---------------- scratch (device globals; no allocation allowed) ----------------
__device__ float g_inorm[Vn];
__device__ float g_hv[Nn*Dn];
__device__ float g_h[Nn*Dn];
__device__ float g_e[En];
__device__ unsigned int g_emax[Nn];
__device__ float g_esum[Nn];
__device__ float g_f[Bn*Dn];
__device__ float g_mscal[Nn];
__device__ float g_srn[Bn*Dn];
__device__ float g_logphi[Bn*2];
__device__ double g_rowsum[Bn];
__device__ double g_msum[Bn];
__device__ int   g_mask_v[Bn*Sn];
__device__ float g_mask_l[Bn*Sn];

// ---------------- helpers ----------------
__device__ __forceinline__ unsigned long long ffma2(unsigned long long a, unsigned long long b, unsigned long long c){
    unsigned long long d;
    asm("fma.rn.f32x2 %0, %1, %2, %3;" : "=l"(d) : "l"(a), "l"(b), "l"(c));
    return d;
}
__device__ __forceinline__ float f2lo(unsigned long long u){ return __int_as_float((int)(unsigned)(u & 0xFFFFFFFFull)); }
__device__ __forceinline__ float f2hi(unsigned long long u){ return __int_as_float((int)(unsigned)(u >> 32)); }
__device__ __forceinline__ unsigned long long fpack(float lo, float hi){
    unsigned long long u;
    asm("mov.b64 %0, {%1, %2};" : "=l"(u) : "r"(__float_as_int(lo)), "r"(__float_as_int(hi)));
    return u;
}
// order-preserving float->uint encoding for atomicMax over signed floats
__device__ __forceinline__ unsigned int fenc(float f){
    int b = __float_as_int(f);
    return (b < 0) ? ~(unsigned int)b : ((unsigned int)b | 0x80000000u);
}
__device__ __forceinline__ float fdec(unsigned int u){
    return (u & 0x80000000u) ? __int_as_float((int)(u & 0x7FFFFFFFu)) : __int_as_float((int)(~u));
}

// ---------------- K0: zero scratch ----------------
__global__ void k_zero(){
    int i = blockIdx.x*blockDim.x + threadIdx.x;
    int stride = gridDim.x*blockDim.x;
    for (int j=i; j<Nn*Dn; j+=stride) g_h[j] = 0.f;
    for (int j=i; j<Nn; j+=stride){ g_esum[j]=0.f; g_emax[j]=0u; }
    for (int j=i; j<Bn; j+=stride){ g_rowsum[j]=0.0; g_msum[j]=0.0; }
}

// ---------------- K1: inverse norms of emb rows ----------------
__global__ void k_inorm(const float* __restrict__ emb){
    int row = blockIdx.x*8 + (threadIdx.x>>5);
    int lane = threadIdx.x&31;
    float ss = 0.f;
    const float* p = emb + (size_t)row*Dn;
    for (int k=lane;k<Dn;k+=32){ float x=p[k]; ss += x*x; }
    #pragma unroll
    for (int o=16;o;o>>=1) ss += __shfl_xor_sync(0xffffffffu, ss, o);
    if (lane==0) g_inorm[row] = 1.f / fmaxf(sqrtf(ss), 1e-12f);
}

// ---------------- K2: h_v = l2norm(emb[iid]) ----------------
__global__ void k_hv(const float* __restrict__ emb, const int* __restrict__ iid){
    int i = blockIdx.x*blockDim.x + threadIdx.x;
    int n = i>>8, k = i&255;
    int id = iid[n];
    g_hv[i] = emb[(size_t)id*Dn + k] * g_inorm[id];
}

// ---------------- K3: edge attention scores + segment max ----------------
__global__ void k_edge(const int* __restrict__ src, const int* __restrict__ dst,
                       const int* __restrict__ dis, const float* __restrict__ dis_emb,
                       const float* __restrict__ pi_w, const float* __restrict__ M_w){
    int e = blockIdx.x*8 + (threadIdx.x>>5);
    int lane = threadIdx.x&31;
    int s = src[e], d = dst[e], di = dis[e];
    const float* hs = g_hv + (size_t)s*Dn;
    const float* hd = g_hv + (size_t)d*Dn;
    const float* he = dis_emb + (size_t)di*Dn;
    float e1 = 0.f, g = 0.f;
    for (int k=lane;k<Dn;k+=32){
        float a = hs[k], b = hd[k], c = he[k];
        float p = a*b;
        e1 += p*c*pi_w[k];
        g  += p*M_w[k] + c*M_w[Dn+k];
    }
    #pragma unroll
    for (int o=16;o;o>>=1){
        e1 += __shfl_xor_sync(0xffffffffu, e1, o);
        g  += __shfl_xor_sync(0xffffffffu, g,  o);
    }
    if (lane==0){
        float ev = e1 * (1.f/(1.f+__expf(-g)));
        g_e[e] = ev;
        atomicMax(&g_emax[d], fenc(ev));
    }
}

// ---------------- K4: exp + segment sum ----------------
__global__ void k_edge_exp(const int* __restrict__ dst){
    int e = blockIdx.x*blockDim.x + threadIdx.x;
    int d = dst[e];
    float mx = fdec(g_emax[d]);
    float ee = __expf(g_e[e]-mx);
    g_e[e] = ee;
    atomicAdd(&g_esum[d], ee);
}

// ---------------- K5: weighted aggregation h = segsum(hs * a) ----------------
__global__ void k_edge_agg(const int* __restrict__ src, const int* __restrict__ dst){
    int e = blockIdx.x*8 + (threadIdx.x>>5);
    int lane = threadIdx.x&31;
    int s = src[e], d = dst[e];
    float a = g_e[e] / g_esum[d];
    const float* hs = g_hv + (size_t)s*Dn;
    float* hp = g_h + (size_t)d*Dn;
    for (int k=lane;k<Dn;k+=32) atomicAdd(&hp[k], hs[k]*a);
}

// ---------------- K6: f = concat(h_t, last_feat) @ r_w   (8 sessions / block) ----------------
__global__ void k_f(const int* __restrict__ tid_, const int* __restrict__ last_idx,
                    const float* __restrict__ target_emb, const float* __restrict__ r_w){
    __shared__ float sin_[8][2*Dn];
    int b0 = blockIdx.x*8;
    int t = threadIdx.x;
    for (int idx=t; idx<8*2*Dn; idx+=256){
        int j = idx>>9, k = idx&511;
        int b = b0+j;
        float v = (k<Dn) ? target_emb[(size_t)tid_[b]*Dn + k]
                         : g_h[(size_t)last_idx[b]*Dn + (k-Dn)];
        sin_[j][k] = v;
    }
    __syncthreads();
    float acc[8] = {0,0,0,0,0,0,0,0};
    int d = t;
    for (int k=0;k<2*Dn;k++){
        float w = r_w[(size_t)k*Dn + d];
        #pragma unroll
        for (int j=0;j<8;j++) acc[j] += sin_[j][k]*w;
    }
    #pragma unroll
    for (int j=0;j<8;j++) g_f[(size_t)(b0+j)*Dn + d] = acc[j];
}

// ---------------- K7: eagg + m-scalar (16 nodes / block), f32x2 inner ----------------
__global__ void __launch_bounds__(256) k_eagg(const int* __restrict__ pid, const int* __restrict__ agg_dst,
                        const float* __restrict__ pos_emb, const float* __restrict__ q_w){
    __shared__ __align__(16) float sT[2*Dn][20];   // [k][j] transposed, padded
    __shared__ int s_pid[16], s_sess[16];
    __shared__ float sred[8][16];
    int j0 = blockIdx.x*16;
    int t = threadIdx.x;
    if (t<16){ s_pid[t] = pid[j0+t]; s_sess[t] = agg_dst[j0+t]; }
    __syncthreads();
    for (int idx=t; idx<16*2*Dn; idx+=256){
        int j = idx>>9, k = idx&511;
        float v = (k<Dn) ? g_h[(size_t)(j0+j)*Dn + k]
                         : pos_emb[(size_t)s_pid[j]*Dn + (k-Dn)];
        sT[k][j] = v;
    }
    __syncthreads();

    unsigned long long acc[8];
    #pragma unroll
    for (int p=0;p<8;p++) acc[p]=0ull;
    int d = t;
    #pragma unroll 4
    for (int k=0;k<2*Dn;k++){
        float w = q_w[(size_t)k*Dn + d];
        unsigned long long wd = fpack(w,w);
        const ulonglong2* sp = (const ulonglong2*)&sT[k][0];
        #pragma unroll
        for (int q=0;q<4;q++){
            ulonglong2 pr = sp[q];
            acc[2*q+0] = ffma2(pr.x, wd, acc[2*q+0]);
            acc[2*q+1] = ffma2(pr.y, wd, acc[2*q+1]);
        }
    }
    float partial[16];
    #pragma unroll
    for (int p=0;p<8;p++){
        float t0 = tanhf(f2lo(acc[p]));
        float t1 = tanhf(f2hi(acc[p]));
        int j = 2*p;
        partial[j]   = t0 * g_f[(size_t)s_sess[j]*Dn + d];
        partial[j+1] = t1 * g_f[(size_t)s_sess[j+1]*Dn + d];
    }
    int w = t>>5, lane = t&31;
    #pragma unroll
    for (int j=0;j<16;j++){
        float p = partial[j];
        #pragma unroll
        for (int o=16;o;o>>=1) p += __shfl_xor_sync(0xffffffffu, p, o);
        if (lane==0) sred[w][j] = p;
    }
    __syncthreads();
    if (t<16){
        float s=0.f;
        #pragma unroll
        for (int ww=0;ww<8;ww++) s += sred[ww][t];
        g_mscal[j0+t] = s;
    }
}

// ---------------- K8: sr = segsum(h*mscal) per session, then l2norm ----------------
__global__ void k_sr(){
    __shared__ float sm[Sn];
    __shared__ float sred[8];
    int b = blockIdx.x, t = threadIdx.x;
    if (t<Sn) sm[t] = g_mscal[b*Sn + t];
    __syncthreads();
    float acc = 0.f;
    #pragma unroll
    for (int s=0;s<Sn;s++) acc += g_h[(size_t)(b*Sn+s)*Dn + t]*sm[s];
    float ss = acc*acc;
    #pragma unroll
    for (int o=16;o;o>>=1) ss += __shfl_xor_sync(0xffffffffu, ss, o);
    if ((t&31)==0) sred[t>>5] = ss;
    __syncthreads();
    float tot = 0.f;
    #pragma unroll
    for (int w=0;w<8;w++) tot += sred[w];
    g_srn[(size_t)b*Dn + t] = acc / fmaxf(sqrtf(tot), 1e-12f);
}

// ---------------- K9: phi head (8 sessions / block) ----------------
__global__ void k_phi(const float* __restrict__ sc1_w, const float* __restrict__ sc1_b,
                      const float* __restrict__ sc2_w){
    __shared__ float ssr[8][Dn];
    __shared__ float s_p[8][2];
    int b0 = blockIdx.x*8;
    int t = threadIdx.x;
    for (int idx=t; idx<8*Dn; idx+=256){
        int j = idx>>8, k = idx&255;
        ssr[j][k] = g_srn[(size_t)(b0+j)*Dn + k];
    }
    if (t<16) s_p[t>>1][t&1] = 0.f;
    __syncthreads();
    float acc[8] = {0,0,0,0,0,0,0,0};
    int d = t;
    for (int k=0;k<Dn;k++){
        float w = sc1_w[(size_t)k*Dn + d];
        #pragma unroll
        for (int j=0;j<8;j++) acc[j] += ssr[j][k]*w;
    }
    float bb = sc1_b[d], w0 = sc2_w[d*2], w1 = sc2_w[d*2+1];
    int lane = t&31, warp = t>>5;
    #pragma unroll
    for (int j=0;j<8;j++){
        float hid = fmaxf(acc[j]+bb, 0.f);
        float p0 = hid*w0, p1 = hid*w1;
        #pragma unroll
        for (int o=16;o;o>>=1){
            p0 += __shfl_xor_sync(0xffffffffu, p0, o);
            p1 += __shfl_xor_sync(0xffffffffu, p1, o);
        }
        if (lane==0){ atomicAdd(&s_p[j][0], p0); atomicAdd(&s_p[j][1], p1); }
    }
    __syncthreads();
    if (t<8){
        float a0 = s_p[t][0], a1 = s_p[t][1];
        float m = fmaxf(a0,a1);
        float lse = m + logf(__expf(a0-m)+__expf(a1-m));
        g_logphi[(b0+t)*2+0] = a0 - lse;
        g_logphi[(b0+t)*2+1] = a1 - lse;
    }
}

// ---------------- K10: masked (in-session) logits + msum ----------------
__global__ void k_masked(const int* __restrict__ iid, const float* __restrict__ emb){
    __shared__ int iids[Sn];
    __shared__ float s_sr[Dn];
    int b = blockIdx.x, t = threadIdx.x;
    if (t<Sn) iids[t] = iid[b*Sn+t];
    if (t<Dn) s_sr[t] = g_srn[(size_t)b*Dn + t];
    __syncthreads();
    int warp = t>>5, lane = t&31;
    for (int slot=warp; slot<Sn; slot+=8){
        int v = iids[slot];
        bool dup = false;
        for (int j=0;j<slot;j++) if (iids[j]==v) { dup=true; break; }
        if (dup){
            if (lane==0) g_mask_v[b*Sn+slot] = -1;
            continue;
        }
        const float* ev = emb + (size_t)v*Dn;
        float dot = 0.f;
        for (int k=lane;k<Dn;k+=32) dot += s_sr[k]*ev[k];
        #pragma unroll
        for (int o=16;o;o>>=1) dot += __shfl_xor_sync(0xffffffffu, dot, o);
        if (lane==0){
            float l = dot * g_inorm[v] * 12.f;
            g_mask_v[b*Sn+slot] = v;
            g_mask_l[b*Sn+slot] = l;
            atomicAdd(&g_msum[b], (double)__expf(l-12.f));
        }
    }
}

// ---------------- K11: big GEMM 12*(srn @ emb^T)*inorm with row-sum epilogue ----------------
// 128x128 tile, 256 threads, 8x8 per thread, f32x2 packed FMA
__global__ void __launch_bounds__(256,2) k_gemm(const float* __restrict__ emb, float* __restrict__ out){
    __shared__ __align__(16) float  As[16][132];   // [k][m]
    __shared__ __align__(16) float2 Bs[16][132];   // [k][n] duplicated pairs
    int t = threadIdx.x;
    int tx = t & 15, ty = t >> 4;
    int m0 = blockIdx.y * 128;
    int v0 = blockIdx.x * 128;

    unsigned long long acc[4][8];
    #pragma unroll
    for (int i=0;i<4;i++)
        #pragma unroll
        for (int j=0;j<8;j++) acc[i][j]=0ull;

    const float4 z4 = make_float4(0.f,0.f,0.f,0.f);
    for (int kt=0; kt<Dn; kt+=16){
        #pragma unroll
        for (int p=0;p<2;p++){
            int linear = p*1024 + t*4;
            int m = linear>>4, k = linear&15;
            float4 a = *(const float4*)(g_srn + (size_t)(m0+m)*Dn + kt + k);
            As[k+0][m]=a.x; As[k+1][m]=a.y; As[k+2][m]=a.z; As[k+3][m]=a.w;
        }
        #pragma unroll
        for (int p=0;p<2;p++){
            int linear = p*1024 + t*4;
            int n = linear>>4, k = linear&15;
            int v = v0+n;
            float4 bq = (v<Vn) ? *(const float4*)(emb + (size_t)v*Dn + kt + k) : z4;
            Bs[k+0][n]=make_float2(bq.x,bq.x);
            Bs[k+1][n]=make_float2(bq.y,bq.y);
            Bs[k+2][n]=make_float2(bq.z,bq.z);
            Bs[k+3][n]=make_float2(bq.w,bq.w);
        }
        __syncthreads();
        #pragma unroll
        for (int k=0;k<16;k++){
            ulonglong2 aA = *(const ulonglong2*)&As[k][ty*8];
            ulonglong2 aB = *(const ulonglong2*)&As[k][ty*8+4];
            unsigned long long a2[4] = {aA.x, aA.y, aB.x, aB.y};
            const ulonglong2* bp = (const ulonglong2*)&Bs[k][tx*8];
            ulonglong2 b01 = bp[0], b23 = bp[1], b45 = bp[2], b67 = bp[3];
            unsigned long long bd[8] = {b01.x,b01.y,b23.x,b23.y,b45.x,b45.y,b67.x,b67.y};
            #pragma unroll
            for (int mi=0;mi<4;mi++)
                #pragma unroll
                for (int n=0;n<8;n++)
                    acc[mi][n] = ffma2(a2[mi], bd[n], acc[mi][n]);
        }
        __syncthreads();
    }

    // epilogue
    bool ok = (v0 + tx*8) < Vn;
    float inv12[8];
    #pragma unroll
    for (int n=0;n<8;n++) inv12[n] = ok ? 12.f*g_inorm[v0+tx*8+n] : 0.f;

    float rexp[8];
    #pragma unroll
    for (int r=0;r<8;r++){
        int mi = r>>1; bool hi = r&1;
        float c[8];
        #pragma unroll
        for (int n=0;n<8;n++){
            unsigned long long u = acc[mi][n];
            float val = hi ? f2hi(u) : f2lo(u);
            c[n] = val*inv12[n];
        }
        float s = 0.f;
        if (ok){
            int row = m0 + ty*8 + r;
            float4* op = (float4*)(out + (size_t)row*Vn + v0 + tx*8);
            __stcs(op,   make_float4(c[0],c[1],c[2],c[3]));
            __stcs(op+1, make_float4(c[4],c[5],c[6],c[7]));
            #pragma unroll
            for (int n=0;n<8;n++) s += __expf(c[n]-12.f);
        }
        rexp[r] = s;
    }
    #pragma unroll
    for (int o=8;o;o>>=1)
        #pragma unroll
        for (int r=0;r<8;r++) rexp[r] += __shfl_xor_sync(0xffffffffu, rexp[r], o);
    if (tx==0){
        #pragma unroll
        for (int r=0;r<8;r++) atomicAdd(&g_rowsum[m0+ty*8+r], (double)rexp[r]);
    }
}

// ---------------- K12: per-row shift for unmasked entries ----------------
__global__ void k_finalize(float* __restrict__ out){
    __shared__ float s_shift;
    int row = blockIdx.y;
    if (threadIdx.x==0){
        double sex = g_rowsum[row] - g_msum[row];
        s_shift = g_logphi[row*2+1] - (float)(12.0 + log(sex));
    }
    __syncthreads();
    float sh = s_shift;
    int i = blockIdx.x*blockDim.x + threadIdx.x;    // float4 index within row
    if (i < Vn/4){
        float4* p = (float4*)(out + (size_t)row*Vn) + i;
        float4 o = __ldcs(p);
        o.x += sh; o.y += sh; o.z += sh; o.w += sh;
        __stcs(p, o);
    }
}

// ---------------- K13: overwrite masked entries ----------------
__global__ void k_fixup(float* __restrict__ out){
    int b = blockIdx.x, s = threadIdx.x;
    if (s >= Sn) return;
    int v = g_mask_v[b*Sn+s];
    if (v < 0) return;
    float lse_in = (float)(12.0 + log(g_msum[b]));
    out[(size_t)b*Vn + v] = g_mask_l[b*Sn+s] - lse_in + g_logphi[b*2+0];
}

// ---------------- launch ----------------
extern "C" void kernel_launch(void* const* d_in, const int* in_sizes, int n_in,
                              void* d_out, int out_size){
    const int* iid      = (const int*)d_in[0];
    const int* src      = (const int*)d_in[1];
    const int* dst      = (const int*)d_in[2];
    const int* dis      = (const int*)d_in[3];
    const int* pid      = (const int*)d_in[4];
    // d_in[5] = agg_src (arange) unused
    const int* agg_dst  = (const int*)d_in[6];
    const int* tid_     = (const int*)d_in[7];
    const int* last_idx = (const int*)d_in[8];
    const float* emb        = (const float*)d_in[9];
    const float* pos_emb    = (const float*)d_in[10];
    const float* dis_emb    = (const float*)d_in[11];
    const float* target_emb = (const float*)d_in[12];
    const float* pi_w  = (const float*)d_in[13];
    const float* M_w   = (const float*)d_in[14];
    const float* q_w   = (const float*)d_in[15];
    const float* r_w   = (const float*)d_in[16];
    const float* sc1_w = (const float*)d_in[17];
    const float* sc1_b = (const float*)d_in[18];
    const float* sc2_w = (const float*)d_in[19];
    float* out = (float*)d_out;

    k_zero<<<512,256>>>();
    k_inorm<<<Vn/8,256>>>(emb);
    k_hv<<<(Nn*Dn)/256,256>>>(emb, iid);
    k_edge<<<En/8,256>>>(src,dst,dis,dis_emb,pi_w,M_w);
    k_edge_exp<<<En/256,256>>>(dst);
    k_edge_agg<<<En/8,256>>>(src,dst);
    k_f<<<Bn/8,256>>>(tid_,last_idx,target_emb,r_w);
    k_eagg<<<Nn/16,256>>>(pid,agg_dst,pos_emb,q_w);
    k_sr<<<Bn,256>>>();
    k_phi<<<Bn/8,256>>>(sc1_w,sc1_b,sc2_w);
    k_masked<<<Bn,256>>>(iid, emb);
    dim3 gg((Vn+127)/128, Bn/128);
    k_gemm<<<gg,256>>>(emb, out);
    dim3 gf((Vn/4 + 255)/256, Bn);
    k_finalize<<<gf,256>>>(out);
    k_fixup<<<Bn,32>>>(out);
}

// round 4
// speedup vs baseline: 1.7134x; 1.7134x over previous
#include <cuda_runtime.h>
#include <math.h>
#include <stdint.h>

#define Vn 100000
#define Dn 256
#define Bn 512
#define Sn 20
#define Nn (Bn*Sn)      // 10240
#define En (8*Nn)       // 81920

// ---------------- scratch (device globals; no allocation allowed) ----------------
__device__ float g_inorm[Vn];
__device__ float g_hv[Nn*Dn];
__device__ float g_h[Nn*Dn];
__device__ float g_e[En];
__device__ unsigned int g_emax[Nn];
__device__ float g_esum[Nn];
__device__ float g_f[Bn*Dn];
__device__ float g_mscal[Nn];
__device__ float g_srn[Bn*Dn];
__device__ float g_logphi[Bn*2];
__device__ double g_rowsum[Bn];
__device__ double g_msum[Bn];
__device__ int   g_mask_v[Bn*Sn];
__device__ float g_mask_l[Bn*Sn];

// ---------------- helpers ----------------
__device__ __forceinline__ unsigned long long ffma2(unsigned long long a, unsigned long long b, unsigned long long c){
    unsigned long long d;
    asm("fma.rn.f32x2 %0, %1, %2, %3;" : "=l"(d) : "l"(a), "l"(b), "l"(c));
    return d;
}
__device__ __forceinline__ float f2lo(unsigned long long u){ return __int_as_float((int)(unsigned)(u & 0xFFFFFFFFull)); }
__device__ __forceinline__ float f2hi(unsigned long long u){ return __int_as_float((int)(unsigned)(u >> 32)); }
__device__ __forceinline__ unsigned long long fpack(float lo, float hi){
    unsigned long long u;
    asm("mov.b64 %0, {%1, %2};" : "=l"(u) : "r"(__float_as_int(lo)), "r"(__float_as_int(hi)));
    return u;
}
__device__ __forceinline__ unsigned int fenc(float f){
    int b = __float_as_int(f);
    return (b < 0) ? ~(unsigned int)b : ((unsigned int)b | 0x80000000u);
}
__device__ __forceinline__ float fdec(unsigned int u){
    return (u & 0x80000000u) ? __int_as_float((int)(u & 0x7FFFFFFFu)) : __int_as_float((int)(~u));
}
__device__ __forceinline__ float tf32r(float x){
    float y; asm("cvt.rna.tf32.f32 %0, %1;" : "=f"(y) : "f"(x)); return y;
}

// mma.sync m16n8k8 tf32: D = A*B + D
#define MMA_TF32(d, a, b0, b1) \
    asm volatile("mma.sync.aligned.m16n8k8.row.col.f32.tf32.tf32.f32 " \
        "{%0,%1,%2,%3}, {%4,%5,%6,%7}, {%8,%9}, {%0,%1,%2,%3};" \
        : "+f"((d)[0]), "+f"((d)[1]), "+f"((d)[2]), "+f"((d)[3]) \
        : "r"((a)[0]), "r"((a)[1]), "r"((a)[2]), "r"((a)[3]), "r"(b0), "r"(b1))

// ---------------- K0: zero scratch ----------------
__global__ void k_zero(){
    int i = blockIdx.x*blockDim.x + threadIdx.x;
    int stride = gridDim.x*blockDim.x;
    for (int j=i; j<Nn*Dn; j+=stride) g_h[j] = 0.f;
    for (int j=i; j<Nn; j+=stride){ g_esum[j]=0.f; g_emax[j]=0u; }
    for (int j=i; j<Bn; j+=stride){ g_rowsum[j]=0.0; g_msum[j]=0.0; }
}

// ---------------- K1: inverse norms of emb rows ----------------
__global__ void k_inorm(const float* __restrict__ emb){
    int row = blockIdx.x*8 + (threadIdx.x>>5);
    int lane = threadIdx.x&31;
    float ss = 0.f;
    const float* p = emb + (size_t)row*Dn;
    for (int k=lane;k<Dn;k+=32){ float x=p[k]; ss += x*x; }
    #pragma unroll
    for (int o=16;o;o>>=1) ss += __shfl_xor_sync(0xffffffffu, ss, o);
    if (lane==0) g_inorm[row] = 1.f / fmaxf(sqrtf(ss), 1e-12f);
}

// ---------------- K2: h_v = l2norm(emb[iid]) ----------------
__global__ void k_hv(const float* __restrict__ emb, const int* __restrict__ iid){
    int i = blockIdx.x*blockDim.x + threadIdx.x;
    int n = i>>8, k = i&255;
    int id = iid[n];
    g_hv[i] = emb[(size_t)id*Dn + k] * g_inorm[id];
}

// ---------------- K3: edge attention scores + segment max ----------------
__global__ void k_edge(const int* __restrict__ src, const int* __restrict__ dst,
                       const int* __restrict__ dis, const float* __restrict__ dis_emb,
                       const float* __restrict__ pi_w, const float* __restrict__ M_w){
    int e = blockIdx.x*8 + (threadIdx.x>>5);
    int lane = threadIdx.x&31;
    int s = src[e], d = dst[e], di = dis[e];
    const float* hs = g_hv + (size_t)s*Dn;
    const float* hd = g_hv + (size_t)d*Dn;
    const float* he = dis_emb + (size_t)di*Dn;
    float e1 = 0.f, g = 0.f;
    for (int k=lane;k<Dn;k+=32){
        float a = hs[k], b = hd[k], c = he[k];
        float p = a*b;
        e1 += p*c*pi_w[k];
        g  += p*M_w[k] + c*M_w[Dn+k];
    }
    #pragma unroll
    for (int o=16;o;o>>=1){
        e1 += __shfl_xor_sync(0xffffffffu, e1, o);
        g  += __shfl_xor_sync(0xffffffffu, g,  o);
    }
    if (lane==0){
        float ev = e1 * (1.f/(1.f+__expf(-g)));
        g_e[e] = ev;
        atomicMax(&g_emax[d], fenc(ev));
    }
}

// ---------------- K4: exp + segment sum ----------------
__global__ void k_edge_exp(const int* __restrict__ dst){
    int e = blockIdx.x*blockDim.x + threadIdx.x;
    int d = dst[e];
    float mx = fdec(g_emax[d]);
    float ee = __expf(g_e[e]-mx);
    g_e[e] = ee;
    atomicAdd(&g_esum[d], ee);
}

// ---------------- K5: weighted aggregation h = segsum(hs * a) ----------------
__global__ void k_edge_agg(const int* __restrict__ src, const int* __restrict__ dst){
    int e = blockIdx.x*8 + (threadIdx.x>>5);
    int lane = threadIdx.x&31;
    int s = src[e], d = dst[e];
    float a = g_e[e] / g_esum[d];
    const float* hs = g_hv + (size_t)s*Dn;
    float* hp = g_h + (size_t)d*Dn;
    for (int k=lane;k<Dn;k+=32) atomicAdd(&hp[k], hs[k]*a);
}

// ---------------- K6: f = concat(h_t, last_feat) @ r_w ----------------
__global__ void k_f(const int* __restrict__ tid_, const int* __restrict__ last_idx,
                    const float* __restrict__ target_emb, const float* __restrict__ r_w){
    __shared__ float sin_[8][2*Dn];
    int b0 = blockIdx.x*8;
    int t = threadIdx.x;
    for (int idx=t; idx<8*2*Dn; idx+=256){
        int j = idx>>9, k = idx&511;
        int b = b0+j;
        float v = (k<Dn) ? target_emb[(size_t)tid_[b]*Dn + k]
                         : g_h[(size_t)last_idx[b]*Dn + (k-Dn)];
        sin_[j][k] = v;
    }
    __syncthreads();
    float acc[8] = {0,0,0,0,0,0,0,0};
    int d = t;
    for (int k=0;k<2*Dn;k++){
        float w = r_w[(size_t)k*Dn + d];
        #pragma unroll
        for (int j=0;j<8;j++) acc[j] += sin_[j][k]*w;
    }
    #pragma unroll
    for (int j=0;j<8;j++) g_f[(size_t)(b0+j)*Dn + d] = acc[j];
}

// ---------------- K7: eagg + m-scalar ----------------
__global__ void __launch_bounds__(256) k_eagg(const int* __restrict__ pid, const int* __restrict__ agg_dst,
                        const float* __restrict__ pos_emb, const float* __restrict__ q_w){
    __shared__ __align__(16) float sT[2*Dn][20];
    __shared__ int s_pid[16], s_sess[16];
    __shared__ float sred[8][16];
    int j0 = blockIdx.x*16;
    int t = threadIdx.x;
    if (t<16){ s_pid[t] = pid[j0+t]; s_sess[t] = agg_dst[j0+t]; }
    __syncthreads();
    for (int idx=t; idx<16*2*Dn; idx+=256){
        int j = idx>>9, k = idx&511;
        float v = (k<Dn) ? g_h[(size_t)(j0+j)*Dn + k]
                         : pos_emb[(size_t)s_pid[j]*Dn + (k-Dn)];
        sT[k][j] = v;
    }
    __syncthreads();

    unsigned long long acc[8];
    #pragma unroll
    for (int p=0;p<8;p++) acc[p]=0ull;
    int d = t;
    #pragma unroll 4
    for (int k=0;k<2*Dn;k++){
        float w = q_w[(size_t)k*Dn + d];
        unsigned long long wd = fpack(w,w);
        const ulonglong2* sp = (const ulonglong2*)&sT[k][0];
        #pragma unroll
        for (int q=0;q<4;q++){
            ulonglong2 pr = sp[q];
            acc[2*q+0] = ffma2(pr.x, wd, acc[2*q+0]);
            acc[2*q+1] = ffma2(pr.y, wd, acc[2*q+1]);
        }
    }
    float partial[16];
    #pragma unroll
    for (int p=0;p<8;p++){
        float t0 = tanhf(f2lo(acc[p]));
        float t1 = tanhf(f2hi(acc[p]));
        int j = 2*p;
        partial[j]   = t0 * g_f[(size_t)s_sess[j]*Dn + d];
        partial[j+1] = t1 * g_f[(size_t)s_sess[j+1]*Dn + d];
    }
    int w = t>>5, lane = t&31;
    #pragma unroll
    for (int j=0;j<16;j++){
        float p = partial[j];
        #pragma unroll
        for (int o=16;o;o>>=1) p += __shfl_xor_sync(0xffffffffu, p, o);
        if (lane==0) sred[w][j] = p;
    }
    __syncthreads();
    if (t<16){
        float s=0.f;
        #pragma unroll
        for (int ww=0;ww<8;ww++) s += sred[ww][t];
        g_mscal[j0+t] = s;
    }
}

// ---------------- K8: sr per session + l2norm ----------------
__global__ void k_sr(){
    __shared__ float sm[Sn];
    __shared__ float sred[8];
    int b = blockIdx.x, t = threadIdx.x;
    if (t<Sn) sm[t] = g_mscal[b*Sn + t];
    __syncthreads();
    float acc = 0.f;
    #pragma unroll
    for (int s=0;s<Sn;s++) acc += g_h[(size_t)(b*Sn+s)*Dn + t]*sm[s];
    float ss = acc*acc;
    #pragma unroll
    for (int o=16;o;o>>=1) ss += __shfl_xor_sync(0xffffffffu, ss, o);
    if ((t&31)==0) sred[t>>5] = ss;
    __syncthreads();
    float tot = 0.f;
    #pragma unroll
    for (int w=0;w<8;w++) tot += sred[w];
    g_srn[(size_t)b*Dn + t] = acc / fmaxf(sqrtf(tot), 1e-12f);
}

// ---------------- K9: phi head ----------------
__global__ void k_phi(const float* __restrict__ sc1_w, const float* __restrict__ sc1_b,
                      const float* __restrict__ sc2_w){
    __shared__ float ssr[8][Dn];
    __shared__ float s_p[8][2];
    int b0 = blockIdx.x*8;
    int t = threadIdx.x;
    for (int idx=t; idx<8*Dn; idx+=256){
        int j = idx>>8, k = idx&255;
        ssr[j][k] = g_srn[(size_t)(b0+j)*Dn + k];
    }
    if (t<16) s_p[t>>1][t&1] = 0.f;
    __syncthreads();
    float acc[8] = {0,0,0,0,0,0,0,0};
    int d = t;
    for (int k=0;k<Dn;k++){
        float w = sc1_w[(size_t)k*Dn + d];
        #pragma unroll
        for (int j=0;j<8;j++) acc[j] += ssr[j][k]*w;
    }
    float bb = sc1_b[d], w0 = sc2_w[d*2], w1 = sc2_w[d*2+1];
    int lane = t&31;
    #pragma unroll
    for (int j=0;j<8;j++){
        float hid = fmaxf(acc[j]+bb, 0.f);
        float p0 = hid*w0, p1 = hid*w1;
        #pragma unroll
        for (int o=16;o;o>>=1){
            p0 += __shfl_xor_sync(0xffffffffu, p0, o);
            p1 += __shfl_xor_sync(0xffffffffu, p1, o);
        }
        if (lane==0){ atomicAdd(&s_p[j][0], p0); atomicAdd(&s_p[j][1], p1); }
    }
    __syncthreads();
    if (t<8){
        float a0 = s_p[t][0], a1 = s_p[t][1];
        float m = fmaxf(a0,a1);
        float lse = m + logf(__expf(a0-m)+__expf(a1-m));
        g_logphi[(b0+t)*2+0] = a0 - lse;
        g_logphi[(b0+t)*2+1] = a1 - lse;
    }
}

// ---------------- K10: masked (in-session) logits + msum ----------------
__global__ void k_masked(const int* __restrict__ iid, const float* __restrict__ emb){
    __shared__ int iids[Sn];
    __shared__ float s_sr[Dn];
    int b = blockIdx.x, t = threadIdx.x;
    if (t<Sn) iids[t] = iid[b*Sn+t];
    if (t<Dn) s_sr[t] = g_srn[(size_t)b*Dn + t];
    __syncthreads();
    int warp = t>>5, lane = t&31;
    for (int slot=warp; slot<Sn; slot+=8){
        int v = iids[slot];
        bool dup = false;
        for (int j=0;j<slot;j++) if (iids[j]==v) { dup=true; break; }
        if (dup){
            if (lane==0) g_mask_v[b*Sn+slot] = -1;
            continue;
        }
        const float* ev = emb + (size_t)v*Dn;
        float dot = 0.f;
        for (int k=lane;k<Dn;k+=32) dot += s_sr[k]*ev[k];
        #pragma unroll
        for (int o=16;o;o>>=1) dot += __shfl_xor_sync(0xffffffffu, dot, o);
        if (lane==0){
            float l = dot * g_inorm[v] * 12.f;
            g_mask_v[b*Sn+slot] = v;
            g_mask_l[b*Sn+slot] = l;
            atomicAdd(&g_msum[b], (double)__expf(l-12.f));
        }
    }
}

// ---------------- K11: mma.sync tf32 3x-split GEMM ----------------
// CTA 128M x 128N, 8 warps (4x2), warp tile 32x64, K chunks of 16, prefetch regs.
// smem: interleaved {hi,lo} float2 panels, row stride 20 float2 (== 4 mod 16 for 2-way max conflicts)
#define PSTRIDE 20
__global__ void __launch_bounds__(256) k_gemm_mma(const float* __restrict__ emb, float* __restrict__ out){
    __shared__ __align__(16) float2 As[128*PSTRIDE];
    __shared__ __align__(16) float2 Bs[128*PSTRIDE];
    int tid = threadIdx.x;
    int w = tid>>5, lane = tid&31;
    int g = lane>>2, t = lane&3;
    int wm = w>>1, wn = w&1;
    int m0 = blockIdx.x*128;       // 0..3
    int v0 = blockIdx.y*128;       // 0..781

    float acc[2][8][4];
    #pragma unroll
    for (int mi=0;mi<2;mi++)
        #pragma unroll
        for (int ni=0;ni<8;ni++)
            #pragma unroll
            for (int q=0;q<4;q++) acc[mi][ni][q]=0.f;

    const float4 z4 = make_float4(0.f,0.f,0.f,0.f);
    float4 pa[2], pb[2];
    // prefetch chunk 0
    #pragma unroll
    for (int it=0; it<2; it++){
        int id = it*256 + tid;
        int row = id>>2, c4 = id&3;
        pa[it] = *(const float4*)(g_srn + (size_t)(m0+row)*Dn + c4*4);
        int vrow = v0 + row;
        pb[it] = (vrow<Vn) ? *(const float4*)(emb + (size_t)vrow*Dn + c4*4) : z4;
    }

    for (int kc=0; kc<16; kc++){
        __syncthreads();
        // store {hi,lo} interleaved
        #pragma unroll
        for (int it=0; it<2; it++){
            int id = it*256 + tid;
            int row = id>>2, c4 = id&3;
            float xs[4] = {pa[it].x, pa[it].y, pa[it].z, pa[it].w};
            float ys[4] = {pb[it].x, pb[it].y, pb[it].z, pb[it].w};
            float2* ap = &As[row*PSTRIDE + c4*4];
            float2* bp = &Bs[row*PSTRIDE + c4*4];
            #pragma unroll
            for (int j=0;j<4;j++){
                float hi = tf32r(xs[j]);
                ap[j] = make_float2(hi, tf32r(xs[j]-hi));
                float hb = tf32r(ys[j]);
                bp[j] = make_float2(hb, tf32r(ys[j]-hb));
            }
        }
        // prefetch next chunk
        if (kc < 15){
            int k0 = (kc+1)*16;
            #pragma unroll
            for (int it=0; it<2; it++){
                int id = it*256 + tid;
                int row = id>>2, c4 = id&3;
                pa[it] = *(const float4*)(g_srn + (size_t)(m0+row)*Dn + k0 + c4*4);
                int vrow = v0 + row;
                pb[it] = (vrow<Vn) ? *(const float4*)(emb + (size_t)vrow*Dn + k0 + c4*4) : z4;
            }
        }
        __syncthreads();
        #pragma unroll
        for (int k8=0; k8<16; k8+=8){
            unsigned ahi[2][4], alo[2][4];
            #pragma unroll
            for (int mi=0;mi<2;mi++){
                int rb = wm*32 + mi*16 + g;
                float2 a0 = As[rb*PSTRIDE + k8+t];
                float2 a1 = As[(rb+8)*PSTRIDE + k8+t];
                float2 a2 = As[rb*PSTRIDE + k8+t+4];
                float2 a3 = As[(rb+8)*PSTRIDE + k8+t+4];
                ahi[mi][0]=__float_as_uint(a0.x); alo[mi][0]=__float_as_uint(a0.y);
                ahi[mi][1]=__float_as_uint(a1.x); alo[mi][1]=__float_as_uint(a1.y);
                ahi[mi][2]=__float_as_uint(a2.x); alo[mi][2]=__float_as_uint(a2.y);
                ahi[mi][3]=__float_as_uint(a3.x); alo[mi][3]=__float_as_uint(a3.y);
            }
            #pragma unroll
            for (int ni=0;ni<8;ni++){
                int nb = wn*64 + ni*8 + g;
                float2 b0 = Bs[nb*PSTRIDE + k8+t];
                float2 b1 = Bs[nb*PSTRIDE + k8+t+4];
                unsigned bh0=__float_as_uint(b0.x), bl0=__float_as_uint(b0.y);
                unsigned bh1=__float_as_uint(b1.x), bl1=__float_as_uint(b1.y);
                #pragma unroll
                for (int mi=0;mi<2;mi++){
                    MMA_TF32(acc[mi][ni], ahi[mi], bh0, bh1);
                    MMA_TF32(acc[mi][ni], ahi[mi], bl0, bl1);
                    MMA_TF32(acc[mi][ni], alo[mi], bh0, bh1);
                }
            }
        }
    }

    // epilogue: scale by 12*inorm, store, accumulate exp row sums
    float rsum[4] = {0.f,0.f,0.f,0.f};
    #pragma unroll
    for (int mi=0;mi<2;mi++){
        int r0 = m0 + wm*32 + mi*16 + g;
        #pragma unroll
        for (int ni=0;ni<8;ni++){
            int col = v0 + wn*64 + ni*8 + 2*t;
            if (col < Vn){
                float s0 = 12.f*g_inorm[col], s1 = 12.f*g_inorm[col+1];
                float v00 = acc[mi][ni][0]*s0, v01 = acc[mi][ni][1]*s1;
                float v10 = acc[mi][ni][2]*s0, v11 = acc[mi][ni][3]*s1;
                float2* p0 = (float2*)(out + (size_t)r0*Vn + col);
                float2* p1 = (float2*)(out + (size_t)(r0+8)*Vn + col);
                __stcs(p0, make_float2(v00, v01));
                __stcs(p1, make_float2(v10, v11));
                rsum[mi*2+0] += __expf(v00-12.f) + __expf(v01-12.f);
                rsum[mi*2+1] += __expf(v10-12.f) + __expf(v11-12.f);
            }
        }
    }
    #pragma unroll
    for (int o=1;o<4;o<<=1)
        #pragma unroll
        for (int j=0;j<4;j++) rsum[j] += __shfl_xor_sync(0xffffffffu, rsum[j], o);
    if (t==0){
        #pragma unroll
        for (int j=0;j<4;j++){
            int row = m0 + wm*32 + (j>>1)*16 + (j&1)*8 + g;
            atomicAdd(&g_rowsum[row], (double)rsum[j]);
        }
    }
}

// ---------------- K12: per-row shift for unmasked entries ----------------
__global__ void k_finalize(float* __restrict__ out){
    __shared__ float s_shift;
    int row = blockIdx.y;
    if (threadIdx.x==0){
        double sex = g_rowsum[row] - g_msum[row];
        s_shift = g_logphi[row*2+1] - (float)(12.0 + log(sex));
    }
    __syncthreads();
    float sh = s_shift;
    int i = blockIdx.x*blockDim.x + threadIdx.x;
    if (i < Vn/4){
        float4* p = (float4*)(out + (size_t)row*Vn) + i;
        float4 o = __ldcs(p);
        o.x += sh; o.y += sh; o.z += sh; o.w += sh;
        __stcs(p, o);
    }
}

// ---------------- K13: overwrite masked entries ----------------
__global__ void k_fixup(float* __restrict__ out){
    int b = blockIdx.x, s = threadIdx.x;
    if (s >= Sn) return;
    int v = g_mask_v[b*Sn+s];
    if (v < 0) return;
    float lse_in = (float)(12.0 + log(g_msum[b]));
    out[(size_t)b*Vn + v] = g_mask_l[b*Sn+s] - lse_in + g_logphi[b*2+0];
}

// ---------------- launch ----------------
extern "C" void kernel_launch(void* const* d_in, const int* in_sizes, int n_in,
                              void* d_out, int out_size){
    const int* iid      = (const int*)d_in[0];
    const int* src      = (const int*)d_in[1];
    const int* dst      = (const int*)d_in[2];
    const int* dis      = (const int*)d_in[3];
    const int* pid      = (const int*)d_in[4];
    const int* agg_dst  = (const int*)d_in[6];
    const int* tid_     = (const int*)d_in[7];
    const int* last_idx = (const int*)d_in[8];
    const float* emb        = (const float*)d_in[9];
    const float* pos_emb    = (const float*)d_in[10];
    const float* dis_emb    = (const float*)d_in[11];
    const float* target_emb = (const float*)d_in[12];
    const float* pi_w  = (const float*)d_in[13];
    const float* M_w   = (const float*)d_in[14];
    const float* q_w   = (const float*)d_in[15];
    const float* r_w   = (const float*)d_in[16];
    const float* sc1_w = (const float*)d_in[17];
    const float* sc1_b = (const float*)d_in[18];
    const float* sc2_w = (const float*)d_in[19];
    float* out = (float*)d_out;

    k_zero<<<512,256>>>();
    k_inorm<<<Vn/8,256>>>(emb);
    k_hv<<<(Nn*Dn)/256,256>>>(emb, iid);
    k_edge<<<En/8,256>>>(src,dst,dis,dis_emb,pi_w,M_w);
    k_edge_exp<<<En/256,256>>>(dst);
    k_edge_agg<<<En/8,256>>>(src,dst);
    k_f<<<Bn/8,256>>>(tid_,last_idx,target_emb,r_w);
    k_eagg<<<Nn/16,256>>>(pid,agg_dst,pos_emb,q_w);
    k_sr<<<Bn,256>>>();
    k_phi<<<Bn/8,256>>>(sc1_w,sc1_b,sc2_w);
    k_masked<<<Bn,256>>>(iid, emb);
    dim3 gg(4, (Vn+127)/128);
    k_gemm_mma<<<gg, 256>>>(emb, out);
    dim3 gf((Vn/4 + 255)/256, Bn);
    k_finalize<<<gf,256>>>(out);
    k_fixup<<<Bn,32>>>(out);
}